// round 3
// baseline (speedup 1.0000x reference)
#include <cuda_runtime.h>
#include <stdint.h>

#define N_NODES 50000
#define DIM     128   // D == O == 128

// Scratch: projected features per relation (25.6 MB each). Static __device__
// arrays are the allowed scratch mechanism (no cudaMalloc permitted).
__device__ float g_x1[N_NODES * DIM];
__device__ float g_x2[N_NODES * DIM];

// ---------------------------------------------------------------------------
// Fused dense projection: x1 = in @ W1, x2 = in @ W2  (K = 128, O = 128)
// Block = 128 threads (one per output column), 16 rows per block.
// inputs tile staged in shared; W accesses are coalesced 512B lines that stay
// L1-resident (64 KB per weight matrix).
// ---------------------------------------------------------------------------
__global__ void __launch_bounds__(128)
gemm_fused_kernel(const float* __restrict__ in,
                  const float* __restrict__ W1,
                  const float* __restrict__ W2)
{
    __shared__ float sh[16 * DIM];

    const int tid  = threadIdx.x;           // output column
    const int row0 = blockIdx.x * 16;       // 50000 / 16 = 3125 exactly

    // Stage 16x128 input tile (coalesced float4 loads).
    const float4* src = reinterpret_cast<const float4*>(in + (size_t)row0 * DIM);
    float4*       dst = reinterpret_cast<float4*>(sh);
    #pragma unroll
    for (int i = tid; i < 16 * (DIM / 4); i += 128)
        dst[i] = src[i];
    __syncthreads();

    float acc1[16], acc2[16];
    #pragma unroll
    for (int r = 0; r < 16; ++r) { acc1[r] = 0.f; acc2[r] = 0.f; }

    #pragma unroll 4
    for (int k = 0; k < DIM; ++k) {
        const float w1 = __ldg(W1 + k * DIM + tid);
        const float w2 = __ldg(W2 + k * DIM + tid);
        #pragma unroll
        for (int r = 0; r < 16; ++r) {
            const float v = sh[r * DIM + k];   // warp-broadcast, conflict-free
            acc1[r] = fmaf(v, w1, acc1[r]);
            acc2[r] = fmaf(v, w2, acc2[r]);
        }
    }

    #pragma unroll
    for (int r = 0; r < 16; ++r) {
        g_x1[(size_t)(row0 + r) * DIM + tid] = acc1[r];
        g_x2[(size_t)(row0 + r) * DIM + tid] = acc2[r];
    }
}

// ---------------------------------------------------------------------------
// COO SpMM scatter: out[row] += val * x[col]   (one warp per edge)
// lane l handles columns [4l, 4l+4) as a float4; scatter uses
// red.global.add.v4.f32 (no-return reduction -> REDG path, 4x fewer atomic
// ops than scalar atomicAdd).
// REL selects the relation's projected-feature buffer.
// ---------------------------------------------------------------------------
template <int REL>
__global__ void __launch_bounds__(256)
spmm_scatter_kernel(const int*   __restrict__ rows,
                    const int*   __restrict__ cols,
                    const float* __restrict__ vals,
                    float*       __restrict__ out,
                    int nE)
{
    const int warp = (blockIdx.x * blockDim.x + threadIdx.x) >> 5;
    const int lane = threadIdx.x & 31;
    if (warp >= nE) return;

    const float* __restrict__ x = (REL == 0) ? g_x1 : g_x2;

    const int   r = __ldg(rows + warp);   // uniform across warp -> 1 request
    const int   c = __ldg(cols + warp);
    const float v = __ldg(vals + warp);

    const float4 xv = __ldg(reinterpret_cast<const float4*>(x + (size_t)c * DIM) + lane);

    float* p = out + (size_t)r * DIM + lane * 4;   // 16B-aligned
    asm volatile("red.global.add.v4.f32 [%0], {%1, %2, %3, %4};"
                 :: "l"(p),
                    "f"(xv.x * v), "f"(xv.y * v), "f"(xv.z * v), "f"(xv.w * v)
                 : "memory");
}

// ---------------------------------------------------------------------------
// In-place ReLU over the accumulated output.
// ---------------------------------------------------------------------------
__global__ void __launch_bounds__(256)
relu_kernel(float* __restrict__ out, int n4)
{
    const int i = blockIdx.x * blockDim.x + threadIdx.x;
    if (i >= n4) return;
    float4 v = reinterpret_cast<float4*>(out)[i];
    v.x = fmaxf(v.x, 0.f);
    v.y = fmaxf(v.y, 0.f);
    v.z = fmaxf(v.z, 0.f);
    v.w = fmaxf(v.w, 0.f);
    reinterpret_cast<float4*>(out)[i] = v;
}

// ---------------------------------------------------------------------------
// Entry point. Inputs (metadata order):
//   0 inputs[N,128] f32 | 1 adj1_rows i32 | 2 adj1_cols i32 | 3 adj1_vals f32
//   4 adj2_rows i32 | 5 adj2_cols i32 | 6 adj2_vals f32
//   7 weights_1[128,128] f32 | 8 weights_2[128,128] f32
// Output: [N,128] f32.
// ---------------------------------------------------------------------------
extern "C" void kernel_launch(void* const* d_in, const int* in_sizes, int n_in,
                              void* d_out, int out_size)
{
    const float* in  = (const float*)d_in[0];
    const int*   a1r = (const int*)  d_in[1];
    const int*   a1c = (const int*)  d_in[2];
    const float* a1v = (const float*)d_in[3];
    const int*   a2r = (const int*)  d_in[4];
    const int*   a2c = (const int*)  d_in[5];
    const float* a2v = (const float*)d_in[6];
    const float* W1  = (const float*)d_in[7];
    const float* W2  = (const float*)d_in[8];
    float*       out = (float*)d_out;

    const int E1 = in_sizes[1];
    const int E2 = in_sizes[4];

    // Output is poisoned before timing; we accumulate with atomics, so zero it.
    cudaMemsetAsync(d_out, 0, (size_t)out_size * sizeof(float));

    // Dense projections (independent of the memset; fine to run concurrently
    // in-order on the same stream).
    gemm_fused_kernel<<<N_NODES / 16, 128>>>(in, W1, W2);

    // Sparse aggregation, one warp per edge (8 warps / 256-thread block).
    const int blk1 = (E1 + 7) / 8;
    const int blk2 = (E2 + 7) / 8;
    spmm_scatter_kernel<0><<<blk1, 256>>>(a1r, a1c, a1v, out, E1);
    spmm_scatter_kernel<1><<<blk2, 256>>>(a2r, a2c, a2v, out, E2);

    // Final activation.
    const int n4 = out_size / 4;
    relu_kernel<<<(n4 + 255) / 256, 256>>>(out, n4);
}

// round 4
// speedup vs baseline: 1.0994x; 1.0994x over previous
#include <cuda_runtime.h>
#include <stdint.h>

#define N_NODES 50000
#define DIM     128      // D == O == 128
#define A_PAD   132      // shared A row stride in floats (bank-conflict-free frags)

// Scratch: projected features per relation (25.6 MB each).
__device__ float g_x1[N_NODES * DIM];
__device__ float g_x2[N_NODES * DIM];

__device__ __forceinline__ uint32_t f2tf32(float f) {
    uint32_t r;
    asm("cvt.rna.tf32.f32 %0, %1;" : "=r"(r) : "f"(f));
    return r;
}

// ---------------------------------------------------------------------------
// Dense projection on tensor cores: x = in @ W per relation (blockIdx.y).
// Block = 256 threads (8 warps) x 64 rows. Warp w owns output cols
// [16w, 16w+16). B fragments (16 cols x 128 k, tf32) are loaded ONCE into
// 64 registers; the K loop is LDS(A-frag) + mma.m16n8k8 only.
// ---------------------------------------------------------------------------
__global__ void __launch_bounds__(256)
gemm_tf32_kernel(const float* __restrict__ in,
                 const float* __restrict__ W1,
                 const float* __restrict__ W2)
{
    __shared__ uint32_t shA[64 * A_PAD];   // 33.8 KB, tf32 bit patterns

    const int tid  = threadIdx.x;
    const int warp = tid >> 5;
    const int lane = tid & 31;
    const int row0 = blockIdx.x * 64;
    const float* __restrict__ W    = blockIdx.y ? W2   : W1;
    float*       __restrict__ xout = blockIdx.y ? g_x2 : g_x1;

    // Stage A tile (64 x 128) -> shared, rounding to tf32 once.
    #pragma unroll
    for (int i = 0; i < 8; ++i) {
        int idx = tid + i * 256;            // 2048 float4 slots
        int r   = idx >> 5;
        int c4  = idx & 31;
        float4 v = make_float4(0.f, 0.f, 0.f, 0.f);
        if (row0 + r < N_NODES)
            v = __ldg(reinterpret_cast<const float4*>(in + (size_t)(row0 + r) * DIM) + c4);
        uint32_t* s = shA + r * A_PAD + c4 * 4;
        s[0] = f2tf32(v.x); s[1] = f2tf32(v.y); s[2] = f2tf32(v.z); s[3] = f2tf32(v.w);
    }
    __syncthreads();

    // B fragments for this warp's 16 columns, all 16 K-steps, both n-tiles.
    // m16n8k8 B layout (col): b0 -> (k = lane%4,   n = lane>>2)
    //                         b1 -> (k = lane%4+4, n = lane>>2)
    const int col0 = warp * 16;
    uint32_t Bf[2][16][2];
    #pragma unroll
    for (int nt = 0; nt < 2; ++nt) {
        const int n = col0 + nt * 8 + (lane >> 2);
        #pragma unroll
        for (int kk = 0; kk < 16; ++kk) {
            const int k = kk * 8 + (lane & 3);
            Bf[nt][kk][0] = f2tf32(__ldg(W + k * DIM + n));
            Bf[nt][kk][1] = f2tf32(__ldg(W + (k + 4) * DIM + n));
        }
    }

    #pragma unroll
    for (int rt = 0; rt < 4; ++rt) {
        float acc[2][4] = {};
        const uint32_t* sA = shA + (rt * 16) * A_PAD;
        #pragma unroll
        for (int kk = 0; kk < 16; ++kk) {
            // A fragment m16k8 (row): a0(r,c) a1(r+8,c) a2(r,c+4) a3(r+8,c+4)
            const int r = lane >> 2, c = kk * 8 + (lane & 3);
            uint32_t a0 = sA[r * A_PAD + c];
            uint32_t a1 = sA[(r + 8) * A_PAD + c];
            uint32_t a2 = sA[r * A_PAD + c + 4];
            uint32_t a3 = sA[(r + 8) * A_PAD + c + 4];
            #pragma unroll
            for (int nt = 0; nt < 2; ++nt) {
                asm volatile(
                    "mma.sync.aligned.m16n8k8.row.col.f32.tf32.tf32.f32 "
                    "{%0,%1,%2,%3}, {%4,%5,%6,%7}, {%8,%9}, {%0,%1,%2,%3};"
                    : "+f"(acc[nt][0]), "+f"(acc[nt][1]),
                      "+f"(acc[nt][2]), "+f"(acc[nt][3])
                    : "r"(a0), "r"(a1), "r"(a2), "r"(a3),
                      "r"(Bf[nt][kk][0]), "r"(Bf[nt][kk][1]));
            }
        }
        // Epilogue: c0,c1 -> (row, 2c..2c+1); c2,c3 -> (row+8, same cols)
        const int rowa = row0 + rt * 16 + (lane >> 2);
        const int rowb = rowa + 8;
        #pragma unroll
        for (int nt = 0; nt < 2; ++nt) {
            const int c = col0 + nt * 8 + 2 * (lane & 3);
            if (rowa < N_NODES)
                *reinterpret_cast<float2*>(xout + (size_t)rowa * DIM + c) =
                    make_float2(acc[nt][0], acc[nt][1]);
            if (rowb < N_NODES)
                *reinterpret_cast<float2*>(xout + (size_t)rowb * DIM + c) =
                    make_float2(acc[nt][2], acc[nt][3]);
        }
    }
}

// ---------------------------------------------------------------------------
// COO SpMM scatter, both relations in ONE launch: one warp per edge,
// lane l owns a float4 of columns, scatter via red.global.add.v4.f32.
// ---------------------------------------------------------------------------
__global__ void __launch_bounds__(256)
spmm_scatter_kernel(const int*   __restrict__ r1, const int*   __restrict__ c1,
                    const float* __restrict__ v1,
                    const int*   __restrict__ r2, const int*   __restrict__ c2,
                    const float* __restrict__ v2,
                    float*       __restrict__ out,
                    int E1, int Etot)
{
    const int e    = (blockIdx.x * blockDim.x + threadIdx.x) >> 5;
    const int lane = threadIdx.x & 31;
    if (e >= Etot) return;

    const float* __restrict__ x;
    int r, c; float v;
    if (e < E1) {
        x = g_x1;
        r = __ldg(r1 + e); c = __ldg(c1 + e); v = __ldg(v1 + e);
    } else {
        const int e2 = e - E1;
        x = g_x2;
        r = __ldg(r2 + e2); c = __ldg(c2 + e2); v = __ldg(v2 + e2);
    }

    const float4 xv = __ldg(reinterpret_cast<const float4*>(x + (size_t)c * DIM) + lane);

    float* p = out + (size_t)r * DIM + lane * 4;   // 16B-aligned
    asm volatile("red.global.add.v4.f32 [%0], {%1, %2, %3, %4};"
                 :: "l"(p),
                    "f"(xv.x * v), "f"(xv.y * v), "f"(xv.z * v), "f"(xv.w * v)
                 : "memory");
}

// ---------------------------------------------------------------------------
// In-place ReLU over the accumulated output.
// ---------------------------------------------------------------------------
__global__ void __launch_bounds__(256)
relu_kernel(float* __restrict__ out, int n4)
{
    const int i = blockIdx.x * blockDim.x + threadIdx.x;
    if (i >= n4) return;
    float4 v = reinterpret_cast<float4*>(out)[i];
    v.x = fmaxf(v.x, 0.f);
    v.y = fmaxf(v.y, 0.f);
    v.z = fmaxf(v.z, 0.f);
    v.w = fmaxf(v.w, 0.f);
    reinterpret_cast<float4*>(out)[i] = v;
}

// ---------------------------------------------------------------------------
// Entry point. Inputs (metadata order):
//   0 inputs[N,128] f32 | 1 adj1_rows i32 | 2 adj1_cols i32 | 3 adj1_vals f32
//   4 adj2_rows i32 | 5 adj2_cols i32 | 6 adj2_vals f32
//   7 weights_1[128,128] f32 | 8 weights_2[128,128] f32
// Output: [N,128] f32.
// ---------------------------------------------------------------------------
extern "C" void kernel_launch(void* const* d_in, const int* in_sizes, int n_in,
                              void* d_out, int out_size)
{
    const float* in  = (const float*)d_in[0];
    const int*   a1r = (const int*)  d_in[1];
    const int*   a1c = (const int*)  d_in[2];
    const float* a1v = (const float*)d_in[3];
    const int*   a2r = (const int*)  d_in[4];
    const int*   a2c = (const int*)  d_in[5];
    const float* a2v = (const float*)d_in[6];
    const float* W1  = (const float*)d_in[7];
    const float* W2  = (const float*)d_in[8];
    float*       out = (float*)d_out;

    const int E1   = in_sizes[1];
    const int E2   = in_sizes[4];
    const int Etot = E1 + E2;

    // Output is poisoned before timing; we accumulate with atomics -> zero it.
    cudaMemsetAsync(d_out, 0, (size_t)out_size * sizeof(float));

    // Tensor-core projections, both relations in one launch (grid.y = relation).
    dim3 ggrid((N_NODES + 63) / 64, 2);
    gemm_tf32_kernel<<<ggrid, 256>>>(in, W1, W2);

    // Sparse aggregation: one warp per edge, both relations in one launch.
    const int blocks = (Etot + 7) / 8;
    spmm_scatter_kernel<<<blocks, 256>>>(a1r, a1c, a1v, a2r, a2c, a2v,
                                         out, E1, Etot);

    // Final activation.
    const int n4 = out_size / 4;
    relu_kernel<<<(n4 + 255) / 256, 256>>>(out, n4);
}